// round 1
// baseline (speedup 1.0000x reference)
#include <cuda_runtime.h>
#include <cuda_bf16.h>

#define BB 32
#define KK 512
#define CC 32
#define TILE 64
#define NT 8   // row tiles per batch (512/64)

// Scratch (no allocations allowed)
__device__ float g_U[BB * KK * CC];        // U[b][k][o] = x[b,k,:]·w_col[o]   (2 MB)
__device__ float g_Vp[BB * NT * CC * KK];  // per-tile partial V[b][t][o][j]   (16 MB)
__device__ float g_s[BB * CC];             // s[b][o]

// ---------------------------------------------------------------------------
// Kernel A: one pass over x. Block = (b, row-tile of 64).
// Thread layout: t in [0,256): o = t>>3 (0..31), jl = t&7 (8-lane j-groups).
// Each thread owns columns j = jl*2 + 16*jj + {0,1}, jj in [0,32): 64 cols as 32 float2.
// Produces U (row dots with w_col) and per-tile V partials (col dots with w_row).
// ---------------------------------------------------------------------------
__global__ __launch_bounds__(256) void kA(const float* __restrict__ x,
                                          const float* __restrict__ wc,
                                          const float* __restrict__ wr) {
    const int b = blockIdx.x;
    const int tile = blockIdx.y;
    const int i0 = tile * TILE;
    const int t = threadIdx.x;
    const int o = t >> 3;
    const int jl = t & 7;

    __shared__ float xs[8 * KK];          // 8 rows of x            (16 KB)
    __shared__ float wr_s[TILE * CC];     // wr_s[r*32+o]           (8 KB)
    __shared__ float U_s[TILE * CC];      // U_s[r*32+o]            (8 KB)

    // preload w_row slice for this row-tile
    for (int idx = t; idx < TILE * CC; idx += 256) {
        int oo = idx & 31, rr = idx >> 5;
        wr_s[idx] = wr[oo * KK + i0 + rr];
    }

    // w_col slice for this thread's (o, j-set), registers
    const float2* wc2 = (const float2*)wc;
    float2 wcr[32];
#pragma unroll
    for (int jj = 0; jj < 32; jj++) wcr[jj] = wc2[o * 256 + jl + 8 * jj];

    float2 Vacc[32];
#pragma unroll
    for (int jj = 0; jj < 32; jj++) Vacc[jj] = make_float2(0.f, 0.f);

    const float4* x4 = (const float4*)x;
    for (int c = 0; c < 8; c++) {
        __syncthreads();
        // load 8 rows (4096 floats) cooperatively as float4
        const size_t f4base = ((size_t)(b * KK + i0 + c * 8)) * (KK / 4);
        float4* xs4 = (float4*)xs;
#pragma unroll
        for (int q = 0; q < 4; q++) xs4[t + q * 256] = x4[f4base + t + q * 256];
        __syncthreads();

#pragma unroll
        for (int r = 0; r < 8; r++) {
            const int row = c * 8 + r;
            const float wrv = wr_s[row * 32 + o];
            const float2* xr2 = (const float2*)(xs + r * KK);
            float u = 0.f;
#pragma unroll
            for (int jj = 0; jj < 32; jj++) {
                float2 xv = xr2[jl + 8 * jj];
                Vacc[jj].x += wrv * xv.x;
                Vacc[jj].y += wrv * xv.y;
                u += wcr[jj].x * xv.x + wcr[jj].y * xv.y;
            }
            // reduce u across the 8-lane j-group (contiguous lanes, xor 1/2/4)
            u += __shfl_xor_sync(0xffffffffu, u, 1);
            u += __shfl_xor_sync(0xffffffffu, u, 2);
            u += __shfl_xor_sync(0xffffffffu, u, 4);
            if (jl == 0) U_s[row * 32 + o] = u;
        }
    }
    __syncthreads();

    // coalesced U writeback: g_U[(b*KK + i0 + r)*CC + o]
    float* Ug = g_U + (size_t)(b * KK + i0) * CC;
    for (int idx = t; idx < TILE * CC; idx += 256) Ug[idx] = U_s[idx];

    // per-tile V partial writeback
    float2* Vg2 = (float2*)(g_Vp + (size_t)(((b * NT + tile) * CC) + o) * KK);
#pragma unroll
    for (int jj = 0; jj < 32; jj++) Vg2[jl + 8 * jj] = Vacc[jj];
}

// ---------------------------------------------------------------------------
// Kernel A2: s[b,o] = sum_k (sum_tiles Vp + b_row[o]) * (U + b_col[o])
// ---------------------------------------------------------------------------
__global__ __launch_bounds__(128) void kA2(const float* __restrict__ bc,
                                           const float* __restrict__ br) {
    const int bo = blockIdx.x;
    const int b = bo >> 5, o = bo & 31;
    const int t = threadIdx.x;
    const float bcv = bc[o], brv = br[o];

    float acc = 0.f;
    for (int k = t; k < KK; k += 128) {
        float u = g_U[(size_t)(b * KK + k) * CC + o] + bcv;
        float v = brv;
#pragma unroll
        for (int tile = 0; tile < NT; tile++)
            v += g_Vp[(size_t)(((b * NT + tile) * CC) + o) * KK + k];
        acc += u * v;
    }
    acc += __shfl_xor_sync(0xffffffffu, acc, 16);
    acc += __shfl_xor_sync(0xffffffffu, acc, 8);
    acc += __shfl_xor_sync(0xffffffffu, acc, 4);
    acc += __shfl_xor_sync(0xffffffffu, acc, 2);
    acc += __shfl_xor_sync(0xffffffffu, acc, 1);

    __shared__ float red[4];
    if ((t & 31) == 0) red[t >> 5] = acc;
    __syncthreads();
    if (t == 0) g_s[bo] = red[0] + red[1] + red[2] + red[3];
}

// ---------------------------------------------------------------------------
// Kernel B: broadcast fill. out[b,o,:,:] = s[b,o]. 1.07 GB of STG.128.
// Block = (bo, chunk of 16384 floats). 16 float4 per thread.
// ---------------------------------------------------------------------------
__global__ __launch_bounds__(256) void kB(float4* __restrict__ out) {
    const int bo = blockIdx.x >> 4;
    const int chunk = blockIdx.x & 15;
    const float v = g_s[bo];
    const float4 val = make_float4(v, v, v, v);
    float4* p = out + (size_t)bo * 65536 + (size_t)chunk * 4096 + threadIdx.x;
#pragma unroll
    for (int q = 0; q < 16; q++) p[q * 256] = val;
}

extern "C" void kernel_launch(void* const* d_in, const int* in_sizes, int n_in,
                              void* d_out, int out_size) {
    const float* x  = (const float*)d_in[0];
    const float* wc = (const float*)d_in[1];
    const float* bc = (const float*)d_in[2];
    const float* wr = (const float*)d_in[3];
    const float* br = (const float*)d_in[4];

    dim3 gA(BB, NT);
    kA<<<gA, 256>>>(x, wc, wr);
    kA2<<<BB * CC, 128>>>(bc, br);
    kB<<<BB * CC * 16, 256>>>((float4*)d_out);
}

// round 3
// speedup vs baseline: 1.1303x; 1.1303x over previous
#include <cuda_runtime.h>
#include <cuda_bf16.h>

#define BB 32
#define KK 512
#define CC 32
#define TILE 128
#define NT 4          // row tiles per batch (512/128)
#define CHUNK 16      // rows staged in smem at a time

// Scratch (no allocations allowed)
__device__ float g_U[BB * KK * CC];        // U[b][k][o] = x[b,k,:]·w_col[o]   (2 MB)
__device__ float g_Vp[BB * NT * CC * KK];  // per-tile partial V[b][t][o][j]   (8 MB)
__device__ float g_s[BB * CC];             // s[b][o]

union F2U { float2 f; unsigned long long u; };
union F4U { float4 f; unsigned long long u[2]; };

__device__ __forceinline__ unsigned long long ffma2(unsigned long long a,
                                                    unsigned long long b,
                                                    unsigned long long c) {
    unsigned long long d;
    asm("fma.rn.f32x2 %0, %1, %2, %3;" : "=l"(d) : "l"(a), "l"(b), "l"(c));
    return d;
}

__device__ __forceinline__ unsigned long long pack2(float v) {
    unsigned long long r;
    asm("mov.b64 %0, {%1, %1};" : "=l"(r) : "f"(v));
    return r;
}

// ---------------------------------------------------------------------------
// Kernel A: one pass over x. Block = (b, 128-row tile), 512 threads.
// Layout: o = t&31 (lane), w = t>>5 (warp = j-slice of 32 cols as 8 float4,
// float4 unit index = w + 16*q, q in [0,8)).
// All shared x reads are full-warp broadcasts (conflict-free, minimal traffic).
// Math in packed f32x2 FMA.
// ---------------------------------------------------------------------------
__global__ __launch_bounds__(512) void kA(const float* __restrict__ x,
                                          const float* __restrict__ wc,
                                          const float* __restrict__ wr) {
    const int b    = blockIdx.x;
    const int tile = blockIdx.y;
    const int i0   = tile * TILE;
    const int t    = threadIdx.x;
    const int o    = t & 31;
    const int w    = t >> 5;

    __shared__ float4 xs4[CHUNK * (KK / 4)];          // 16 rows of x   (32 KB)
    __shared__ float  wr_s[TILE * CC];                // wr_s[r*32+o]   (16 KB)
    __shared__ float  u_part[CHUNK * 16 * CC];        // partial U      (32 KB)

    // preload w_row slice for this row-tile (rows i0..i0+127)
#pragma unroll
    for (int i = 0; i < (TILE * CC) / 512; i++) {
        int idx = t + i * 512;
        int rr = idx >> 5, oo = idx & 31;
        wr_s[idx] = wr[oo * KK + i0 + rr];
    }

    // w_col slice for this thread's (o, j-slice): 8 float4 = 16 packed f32x2
    unsigned long long wcr[16];
#pragma unroll
    for (int q = 0; q < 8; q++) {
        F4U v; v.f = ((const float4*)wc)[o * (KK / 4) + w + 16 * q];
        wcr[2 * q]     = v.u[0];
        wcr[2 * q + 1] = v.u[1];
    }

    unsigned long long Vacc[16];
#pragma unroll
    for (int q = 0; q < 16; q++) Vacc[q] = 0ull;

    const float4* x4 = (const float4*)x;

    for (int c = 0; c < TILE / CHUNK; c++) {
        __syncthreads();
        // stage CHUNK rows (2048 float4), coalesced
        const size_t f4base = ((size_t)(b * KK + i0 + c * CHUNK)) * (KK / 4);
#pragma unroll
        for (int i = 0; i < 4; i++) xs4[t + i * 512] = x4[f4base + t + i * 512];
        __syncthreads();

#pragma unroll
        for (int r = 0; r < CHUNK; r++) {
            const int row = c * CHUNK + r;
            const unsigned long long wr2 = pack2(wr_s[row * 32 + o]);
            const float4* xr4 = xs4 + r * (KK / 4);
            unsigned long long ua = 0ull, ub = 0ull;
#pragma unroll
            for (int q = 0; q < 8; q++) {
                F4U xv; xv.f = xr4[w + 16 * q];            // 32-lane broadcast
                Vacc[2 * q]     = ffma2(wr2, xv.u[0], Vacc[2 * q]);
                Vacc[2 * q + 1] = ffma2(wr2, xv.u[1], Vacc[2 * q + 1]);
                ua = ffma2(wcr[2 * q],     xv.u[0], ua);
                ub = ffma2(wcr[2 * q + 1], xv.u[1], ub);
            }
            F2U us; us.u = ua; F2U ut; ut.u = ub;
            u_part[(r * 16 + w) * 32 + o] = (us.f.x + us.f.y) + (ut.f.x + ut.f.y);
        }
        __syncthreads();

        // reduce u_part across the 16 warps; write U coalesced
        {
            const int rr = t >> 5, oo = t & 31;    // (row-in-chunk, o)
            float s = 0.f;
#pragma unroll
            for (int wi = 0; wi < 16; wi++) s += u_part[(rr * 16 + wi) * 32 + oo];
            g_U[(size_t)(b * KK + i0 + c * CHUNK + rr) * CC + oo] = s;
        }
    }

    // per-tile V partial writeback: g_Vp[((b*NT+tile)*CC+o)*KK + j]
    float4* Vg4 = (float4*)(g_Vp + (size_t)(((b * NT + tile) * CC) + o) * KK);
#pragma unroll
    for (int q = 0; q < 8; q++) {
        F4U v; v.u[0] = Vacc[2 * q]; v.u[1] = Vacc[2 * q + 1];
        Vg4[w + 16 * q] = v.f;
    }
}

// ---------------------------------------------------------------------------
// Kernel A2: s[b,o] = sum_k (sum_tiles Vp + b_row[o]) * (U + b_col[o])
// ---------------------------------------------------------------------------
__global__ __launch_bounds__(128) void kA2(const float* __restrict__ bc,
                                           const float* __restrict__ br) {
    const int bo = blockIdx.x;
    const int b = bo >> 5, o = bo & 31;
    const int t = threadIdx.x;
    const float bcv = bc[o], brv = br[o];

    float acc = 0.f;
    for (int k = t; k < KK; k += 128) {
        float u = g_U[(size_t)(b * KK + k) * CC + o] + bcv;
        float v = brv;
#pragma unroll
        for (int tile = 0; tile < NT; tile++)
            v += g_Vp[(size_t)(((b * NT + tile) * CC) + o) * KK + k];
        acc += u * v;
    }
    acc += __shfl_xor_sync(0xffffffffu, acc, 16);
    acc += __shfl_xor_sync(0xffffffffu, acc, 8);
    acc += __shfl_xor_sync(0xffffffffu, acc, 4);
    acc += __shfl_xor_sync(0xffffffffu, acc, 2);
    acc += __shfl_xor_sync(0xffffffffu, acc, 1);

    __shared__ float red[4];
    if ((t & 31) == 0) red[t >> 5] = acc;
    __syncthreads();
    if (t == 0) g_s[bo] = red[0] + red[1] + red[2] + red[3];
}

// ---------------------------------------------------------------------------
// Kernel B: broadcast fill. out[b,o,:,:] = s[b,o]. 1.07 GB of STG.128.
// ---------------------------------------------------------------------------
__global__ __launch_bounds__(256) void kB(float4* __restrict__ out) {
    const int bo = blockIdx.x >> 4;
    const int chunk = blockIdx.x & 15;
    const float v = g_s[bo];
    const float4 val = make_float4(v, v, v, v);
    float4* p = out + (size_t)bo * 65536 + (size_t)chunk * 4096 + threadIdx.x;
#pragma unroll
    for (int q = 0; q < 16; q++) p[q * 256] = val;
}

extern "C" void kernel_launch(void* const* d_in, const int* in_sizes, int n_in,
                              void* d_out, int out_size) {
    const float* x  = (const float*)d_in[0];
    const float* wc = (const float*)d_in[1];
    const float* bc = (const float*)d_in[2];
    const float* wr = (const float*)d_in[3];
    const float* br = (const float*)d_in[4];

    dim3 gA(BB, NT);
    kA<<<gA, 512>>>(x, wc, wr);
    kA2<<<BB * CC, 128>>>(bc, br);
    kB<<<BB * CC * 16, 256>>>((float4*)d_out);
}

// round 5
// speedup vs baseline: 1.1585x; 1.0249x over previous
#include <cuda_runtime.h>
#include <cuda_bf16.h>
#include <stdint.h>

#define BB 32
#define KK 512
#define CC 32
#define TILE 128
#define NT 4          // row tiles per batch (512/128)
#define CHUNK 16      // rows staged in smem at a time
#define NCH (TILE / CHUNK)   // 8 chunks

// Scratch (no allocations allowed)
__device__ float g_U[BB * KK * CC];        // U[b][k][o] = x[b,k,:]·w_col[o]   (2 MB)
__device__ float g_Vp[BB * NT * CC * KK];  // per-tile partial V[b][t][o][j]   (8 MB)
__device__ float g_s[BB * CC];             // s[b][o]

union F2U { float2 f; unsigned long long u; };
union F4U { float4 f; unsigned long long u[2]; };

__device__ __forceinline__ unsigned long long ffma2(unsigned long long a,
                                                    unsigned long long b,
                                                    unsigned long long c) {
    unsigned long long d;
    asm("fma.rn.f32x2 %0, %1, %2, %3;" : "=l"(d) : "l"(a), "l"(b), "l"(c));
    return d;
}

__device__ __forceinline__ unsigned long long pack2(float v) {
    unsigned long long r;
    asm("mov.b64 %0, {%1, %1};" : "=l"(r) : "f"(v));
    return r;
}

__device__ __forceinline__ void cp16(uint32_t smem_addr, const void* gptr) {
    asm volatile("cp.async.cg.shared.global [%0], [%1], 16;"
                 :: "r"(smem_addr), "l"(gptr));
}

// ---------------------------------------------------------------------------
// Kernel A: one pass over x. Block = (b, 128-row tile), 512 threads.
// o = t&31 (lane), w = t>>5 (warp = j-slice: 32 cols as 8 float4 at w+16q).
// cp.async double-buffered x staging; double-buffered cross-warp U reduce;
// ONE __syncthreads per chunk. Math in packed f32x2 FMA.
// ---------------------------------------------------------------------------
__global__ __launch_bounds__(512) void kA(const float* __restrict__ x,
                                          const float* __restrict__ wc,
                                          const float* __restrict__ wr) {
    const int b    = blockIdx.x;
    const int tile = blockIdx.y;
    const int i0   = tile * TILE;
    const int t    = threadIdx.x;
    const int o    = t & 31;
    const int w    = t >> 5;

    __shared__ float4 xs4[2][CHUNK * (KK / 4)];        // 2 x 32 KB
    __shared__ float  wr_s[TILE * CC];                 // 16 KB
    __shared__ float  u_part[2][CHUNK * 16 * CC];      // 2 x 32 KB

    const float4* x4 = (const float4*)x;
    const size_t  xbase = (size_t)(b * KK + i0) * (KK / 4);
    const uint32_t xs_sa[2] = {
        (uint32_t)__cvta_generic_to_shared(&xs4[0][0]),
        (uint32_t)__cvta_generic_to_shared(&xs4[1][0])
    };

    // prefetch chunk 0
    {
        const float4* src = x4 + xbase;
#pragma unroll
        for (int i = 0; i < 4; i++)
            cp16(xs_sa[0] + (uint32_t)(t + i * 512) * 16u, src + t + i * 512);
        asm volatile("cp.async.commit_group;");
    }

    // preload w_row slice for this row-tile (rows i0..i0+127)
#pragma unroll
    for (int i = 0; i < (TILE * CC) / 512; i++) {
        int idx = t + i * 512;
        int rr = idx >> 5, oo = idx & 31;
        wr_s[idx] = wr[oo * KK + i0 + rr];
    }

    // w_col slice for this thread's (o, j-slice): 8 float4 = 16 packed f32x2
    unsigned long long wcr[16];
#pragma unroll
    for (int q = 0; q < 8; q++) {
        F4U v; v.f = ((const float4*)wc)[o * (KK / 4) + w + 16 * q];
        wcr[2 * q]     = v.u[0];
        wcr[2 * q + 1] = v.u[1];
    }

    unsigned long long Vacc[16];
#pragma unroll
    for (int q = 0; q < 16; q++) Vacc[q] = 0ull;

    for (int c = 0; c < NCH; c++) {
        asm volatile("cp.async.wait_group 0;" ::: "memory");
        __syncthreads();   // xs[c&1] ready everywhere; all reads of xs[(c+1)&1] done

        // prefetch chunk c+1 into the other buffer (overlaps with compute below)
        if (c + 1 < NCH) {
            const float4* src = x4 + xbase + (size_t)(c + 1) * CHUNK * (KK / 4);
            const uint32_t dst = xs_sa[(c + 1) & 1];
#pragma unroll
            for (int i = 0; i < 4; i++)
                cp16(dst + (uint32_t)(t + i * 512) * 16u, src + t + i * 512);
            asm volatile("cp.async.commit_group;");
        }

        // reduce previous chunk's U partials (reads u_part[(c-1)&1])
        if (c > 0) {
            const int pc = c - 1;
            const int rr = t >> 5, oo = t & 31;
            float s = 0.f;
#pragma unroll
            for (int wi = 0; wi < 16; wi++)
                s += u_part[pc & 1][(rr * 16 + wi) * 32 + oo];
            g_U[(size_t)(b * KK + i0 + pc * CHUNK + rr) * CC + oo] = s;
        }

        // compute chunk c (writes u_part[c&1])
        const float4* xsb = xs4[c & 1];
        float* upb = u_part[c & 1];
#pragma unroll
        for (int r = 0; r < CHUNK; r++) {
            const int row = c * CHUNK + r;
            const unsigned long long wr2 = pack2(wr_s[row * 32 + o]);
            const float4* xr4 = xsb + r * (KK / 4);
            unsigned long long ua = 0ull, ub = 0ull;
#pragma unroll
            for (int q = 0; q < 8; q++) {
                F4U xv; xv.f = xr4[w + 16 * q];            // 32-lane broadcast
                Vacc[2 * q]     = ffma2(wr2, xv.u[0], Vacc[2 * q]);
                Vacc[2 * q + 1] = ffma2(wr2, xv.u[1], Vacc[2 * q + 1]);
                ua = ffma2(wcr[2 * q],     xv.u[0], ua);
                ub = ffma2(wcr[2 * q + 1], xv.u[1], ub);
            }
            F2U us; us.u = ua; F2U ut; ut.u = ub;
            upb[(r * 16 + w) * 32 + o] = (us.f.x + us.f.y) + (ut.f.x + ut.f.y);
        }
    }

    __syncthreads();
    // reduce last chunk's U partials
    {
        const int pc = NCH - 1;
        const int rr = t >> 5, oo = t & 31;
        float s = 0.f;
#pragma unroll
        for (int wi = 0; wi < 16; wi++)
            s += u_part[pc & 1][(rr * 16 + wi) * 32 + oo];
        g_U[(size_t)(b * KK + i0 + pc * CHUNK + rr) * CC + oo] = s;
    }

    // per-tile V partial writeback: g_Vp[((b*NT+tile)*CC+o)*KK + j]
    float4* Vg4 = (float4*)(g_Vp + (size_t)(((b * NT + tile) * CC) + o) * KK);
#pragma unroll
    for (int q = 0; q < 8; q++) {
        F4U v; v.u[0] = Vacc[2 * q]; v.u[1] = Vacc[2 * q + 1];
        Vg4[w + 16 * q] = v.f;
    }
}

// ---------------------------------------------------------------------------
// Kernel A2: s[b,o] = sum_k (sum_tiles Vp + b_row[o]) * (U + b_col[o])
// ---------------------------------------------------------------------------
__global__ __launch_bounds__(128) void kA2(const float* __restrict__ bc,
                                           const float* __restrict__ br) {
    const int bo = blockIdx.x;
    const int b = bo >> 5, o = bo & 31;
    const int t = threadIdx.x;
    const float bcv = bc[o], brv = br[o];

    float acc = 0.f;
    for (int k = t; k < KK; k += 128) {
        float u = g_U[(size_t)(b * KK + k) * CC + o] + bcv;
        float v = brv;
#pragma unroll
        for (int tile = 0; tile < NT; tile++)
            v += g_Vp[(size_t)(((b * NT + tile) * CC) + o) * KK + k];
        acc += u * v;
    }
    acc += __shfl_xor_sync(0xffffffffu, acc, 16);
    acc += __shfl_xor_sync(0xffffffffu, acc, 8);
    acc += __shfl_xor_sync(0xffffffffu, acc, 4);
    acc += __shfl_xor_sync(0xffffffffu, acc, 2);
    acc += __shfl_xor_sync(0xffffffffu, acc, 1);

    __shared__ float red[4];
    if ((t & 31) == 0) red[t >> 5] = acc;
    __syncthreads();
    if (t == 0) g_s[bo] = red[0] + red[1] + red[2] + red[3];
}

// ---------------------------------------------------------------------------
// Kernel B: broadcast fill. out[b,o,:,:] = s[b,o]. 1.07 GB of STG.128.
// ---------------------------------------------------------------------------
__global__ __launch_bounds__(256) void kB(float4* __restrict__ out) {
    const int bo = blockIdx.x >> 4;
    const int chunk = blockIdx.x & 15;
    const float v = g_s[bo];
    const float4 val = make_float4(v, v, v, v);
    float4* p = out + (size_t)bo * 65536 + (size_t)chunk * 4096 + threadIdx.x;
#pragma unroll
    for (int q = 0; q < 16; q++) p[q * 256] = val;
}

extern "C" void kernel_launch(void* const* d_in, const int* in_sizes, int n_in,
                              void* d_out, int out_size) {
    const float* x  = (const float*)d_in[0];
    const float* wc = (const float*)d_in[1];
    const float* bc = (const float*)d_in[2];
    const float* wr = (const float*)d_in[3];
    const float* br = (const float*)d_in[4];

    dim3 gA(BB, NT);
    kA<<<gA, 512>>>(x, wc, wr);
    kA2<<<BB * CC, 128>>>(bc, br);
    kB<<<BB * CC * 16, 256>>>((float4*)d_out);
}